// round 6
// baseline (speedup 1.0000x reference)
#include <cuda_runtime.h>
#include <cuda_bf16.h>
#include <cstdint>

#define NE    8
#define NTOK  4096
#define DH    2048
#define DE    1024
#define MAXTILES 104
#define MAXROWS  (MAXTILES*128)   // 13312

// ---------------- device-global scratch (static, no allocation) ----------------
__device__ __align__(16) __nv_bfloat16 g_Xhi[(size_t)MAXROWS*DH];
__device__ __align__(16) __nv_bfloat16 g_Xlo[(size_t)MAXROWS*DH];
__device__ __align__(16) __nv_bfloat16 g_Hhi[(size_t)MAXROWS*DE];
__device__ __align__(16) __nv_bfloat16 g_Hlo[(size_t)MAXROWS*DE];
__device__ __align__(16) float         g_Y  [(size_t)MAXROWS*DH];
// weights, bf16 hi/lo, transposed to [e][N][K] (K contiguous). 9th "expert" = shared.
__device__ __align__(16) __nv_bfloat16 g_Wgh[(size_t)9*DE*DH];
__device__ __align__(16) __nv_bfloat16 g_Wgl[(size_t)9*DE*DH];
__device__ __align__(16) __nv_bfloat16 g_Wuh[(size_t)9*DE*DH];
__device__ __align__(16) __nv_bfloat16 g_Wul[(size_t)9*DE*DH];
__device__ __align__(16) __nv_bfloat16 g_Wdh[(size_t)9*DE*DH];
__device__ __align__(16) __nv_bfloat16 g_Wdl[(size_t)9*DE*DH];

__device__ int   g_tok[NE*NTOK];
__device__ float g_wt [NE*NTOK];
__device__ int   g_cnt[NE];
__device__ int   g_off[10];
__device__ int   g_route[NTOK*2];     // (e<<20)|slot
__device__ float g_rowwt[MAXROWS];
__device__ int   g_tile_e[MAXTILES];
__device__ int   g_ntiles, g_total;

// ---------------- helpers ----------------
__device__ __forceinline__ void bsplit(float v, __nv_bfloat16& h, __nv_bfloat16& l) {
    h = __float2bfloat16(v);
    l = __float2bfloat16(v - __bfloat162float(h));
}
__device__ __forceinline__ void cp16(void* s, const void* g) {
    uint32_t sa = (uint32_t)__cvta_generic_to_shared(s);
    asm volatile("cp.async.cg.shared.global [%0], [%1], 16;\n" :: "r"(sa), "l"(g));
}
__device__ __forceinline__ void cp_commit() { asm volatile("cp.async.commit_group;\n"); }
template<int N> __device__ __forceinline__ void cp_wait() {
    asm volatile("cp.async.wait_group %0;\n" :: "n"(N));
}
__device__ __forceinline__ void ldm4(uint32_t* r, const void* p) {
    uint32_t a = (uint32_t)__cvta_generic_to_shared(p);
    asm volatile("ldmatrix.sync.aligned.m8n8.x4.shared.b16 {%0,%1,%2,%3},[%4];\n"
                 : "=r"(r[0]), "=r"(r[1]), "=r"(r[2]), "=r"(r[3]) : "r"(a));
}
__device__ __forceinline__ void mma16816(float* c, const uint32_t* a, const uint32_t* b) {
    asm volatile(
        "mma.sync.aligned.m16n8k16.row.col.f32.bf16.bf16.f32 "
        "{%0,%1,%2,%3},{%4,%5,%6,%7},{%8,%9},{%0,%1,%2,%3};\n"
        : "+f"(c[0]), "+f"(c[1]), "+f"(c[2]), "+f"(c[3])
        : "r"(a[0]), "r"(a[1]), "r"(a[2]), "r"(a[3]), "r"(b[0]), "r"(b[1]));
}

// ---------------- 1. init ----------------
__global__ void init_kernel() { if (threadIdx.x < NE) g_cnt[threadIdx.x] = 0; }

// ---------------- 2. router: warp per token ----------------
__global__ void router_kernel(const float* __restrict__ x, const float* __restrict__ Wg) {
    int warp = threadIdx.x >> 5, lane = threadIdx.x & 31;
    int t = blockIdx.x * 8 + warp;
    if (t >= NTOK) return;
    const float* xr = x + (size_t)t * DH;
    float acc[NE];
#pragma unroll
    for (int e = 0; e < NE; e++) acc[e] = 0.f;
    for (int d = lane; d < DH; d += 32) {
        float xv = xr[d];
        const float* wr = Wg + (size_t)d * NE;
#pragma unroll
        for (int e = 0; e < NE; e++) acc[e] += xv * wr[e];
    }
#pragma unroll
    for (int o = 16; o; o >>= 1)
#pragma unroll
        for (int e = 0; e < NE; e++) acc[e] += __shfl_down_sync(0xFFFFFFFFu, acc[e], o);
    if (lane == 0) {
        float m = acc[0];
#pragma unroll
        for (int e = 1; e < NE; e++) m = fmaxf(m, acc[e]);
        float p[NE], s = 0.f;
#pragma unroll
        for (int e = 0; e < NE; e++) { p[e] = __expf(acc[e] - m); s += p[e]; }
        float inv = 1.f / s;
#pragma unroll
        for (int e = 0; e < NE; e++) p[e] *= inv;
        int e0 = 0; float b0 = p[0];
#pragma unroll
        for (int e = 1; e < NE; e++) if (p[e] > b0) { b0 = p[e]; e0 = e; }
        int e1 = -1; float b1 = -1.f;
#pragma unroll
        for (int e = 0; e < NE; e++) if (e != e0 && p[e] > b1) { b1 = p[e]; e1 = e; }
        int s0 = atomicAdd(&g_cnt[e0], 1);
        g_tok[e0*NTOK + s0] = t; g_wt[e0*NTOK + s0] = b0;
        int s1 = atomicAdd(&g_cnt[e1], 1);
        g_tok[e1*NTOK + s1] = t; g_wt[e1*NTOK + s1] = b1;
        g_route[t*2 + 0] = (e0 << 20) | s0;
        g_route[t*2 + 1] = (e1 << 20) | s1;
    }
}

// ---------------- 3. offsets + tile map ----------------
__global__ void offsets_kernel() {
    if (threadIdx.x != 0) return;
    int off = 0, tc = 0;
    for (int e = 0; e < 9; e++) {
        g_off[e] = off;
        int c = (e < NE) ? g_cnt[e] : NTOK;
        int nt = (c + 127) >> 7;
        for (int i = 0; i < nt; i++) g_tile_e[tc + i] = e;
        tc += nt; off += nt << 7;
    }
    g_off[9] = off; g_ntiles = tc; g_total = off;
}

// ---------------- 4. gather + fp32->bf16 split (one block per padded row) ----------------
__global__ void gather_kernel(const float* __restrict__ x) {
    int r = blockIdx.x;
    if (r >= g_total) return;
    int e = 8;
#pragma unroll
    for (int i = 0; i < 9; i++) if (r < g_off[i+1]) { e = i; break; }
    int s = r - g_off[e];
    int t = -1; float wt = 0.f;
    if (e < NE) {
        if (s < g_cnt[e]) { t = g_tok[e*NTOK + s]; wt = g_wt[e*NTOK + s]; }
    } else { t = s; wt = 1.f; }
    if (threadIdx.x == 0) g_rowwt[r] = wt;
    __nv_bfloat16* dh = g_Xhi + (size_t)r * DH;
    __nv_bfloat16* dl = g_Xlo + (size_t)r * DH;
    if (t >= 0) {
        const float4* src = (const float4*)(x + (size_t)t * DH);
        for (int i = threadIdx.x; i < DH/4; i += blockDim.x) {
            float4 v = src[i];
            __nv_bfloat16 hx,lx,hy,ly,hz,lz,hw,lw;
            bsplit(v.x,hx,lx); bsplit(v.y,hy,ly); bsplit(v.z,hz,lz); bsplit(v.w,hw,lw);
            ((__nv_bfloat162*)dh)[i*2+0] = __nv_bfloat162(hx,hy);
            ((__nv_bfloat162*)dh)[i*2+1] = __nv_bfloat162(hz,hw);
            ((__nv_bfloat162*)dl)[i*2+0] = __nv_bfloat162(lx,ly);
            ((__nv_bfloat162*)dl)[i*2+1] = __nv_bfloat162(lz,lw);
        }
    } else {
        uint4 z = {0,0,0,0};
        for (int i = threadIdx.x; i < DH*2/16; i += blockDim.x) {
            ((uint4*)dh)[i] = z; ((uint4*)dl)[i] = z;
        }
    }
}

// ---------------- 5. weight transpose + split: [e][K][N] f32 -> [e][N][K] bf16 hi/lo ----
template<int W>  // 0=gate 1=up 2=down
__global__ void wsplit_kernel(const float* __restrict__ Wr, const float* __restrict__ Ws) {
    constexpr int K = (W == 2) ? DE : DH;
    constexpr int N = (W == 2) ? DH : DE;
    __nv_bfloat16* dh = (W==0) ? g_Wgh : (W==1) ? g_Wuh : g_Wdh;
    __nv_bfloat16* dl = (W==0) ? g_Wgl : (W==1) ? g_Wul : g_Wdl;
    int e = blockIdx.z;
    const float* src = (e < NE) ? (Wr + (size_t)e * K * N) : Ws;
    __nv_bfloat16* oh = dh + (size_t)e * K * N;
    __nv_bfloat16* ol = dl + (size_t)e * K * N;
    __shared__ float tile[32][33];
    int n0 = blockIdx.x * 32, k0 = blockIdx.y * 32;
    int tx = threadIdx.x & 31, ty = threadIdx.x >> 5;
#pragma unroll
    for (int j = 0; j < 4; j++) {
        int k = ty + j*8;
        tile[k][tx] = src[(size_t)(k0+k)*N + n0 + tx];
    }
    __syncthreads();
#pragma unroll
    for (int j = 0; j < 4; j++) {
        int n = ty + j*8;
        float v = tile[tx][n];
        __nv_bfloat16 h, l; bsplit(v, h, l);
        size_t o = (size_t)(n0+n)*K + k0 + tx;
        oh[o] = h; ol[o] = l;
    }
}

// ---------------- 6. grouped GEMM (mma.sync bf16, 3-term split) ----------------
// Block: 128M x 64N, 256 thr, warps 4x2, warp tile 32x32. K chunk 32, double-buffered.
// FUSE=1: A=Xhi/Xlo (K=2048), B=gate&up, epilogue silu(g)*u*wt -> Hhi/Hlo
// FUSE=0: A=Hhi/Hlo (K=1024), B=down, epilogue -> Y (f32)
#define SMSTRIDE 40   // elements per smem row (80B, conflict-free for ldmatrix)

template<bool FUSE>
__global__ void __launch_bounds__(256) gemm_kernel() {
    int tm = blockIdx.y;
    if (tm >= g_ntiles) return;
    constexpr int K = FUSE ? DH : DE;
    int e = g_tile_e[tm];
    int row0 = tm * 128;
    int n0 = blockIdx.x * 64;

    const __nv_bfloat16* Ah_g = (FUSE ? g_Xhi : g_Hhi) + (size_t)row0 * K;
    const __nv_bfloat16* Al_g = (FUSE ? g_Xlo : g_Hlo) + (size_t)row0 * K;
    const __nv_bfloat16* B0h = (FUSE ? g_Wgh : g_Wdh) + (size_t)e*DE*DH + (size_t)n0*K;
    const __nv_bfloat16* B0l = (FUSE ? g_Wgl : g_Wdl) + (size_t)e*DE*DH + (size_t)n0*K;
    const __nv_bfloat16* B1h = g_Wuh + (size_t)e*DE*DH + (size_t)n0*K;
    const __nv_bfloat16* B1l = g_Wul + (size_t)e*DE*DH + (size_t)n0*K;

    extern __shared__ char smem[];
    constexpr int OFF_AL = 128*SMSTRIDE*2;        // 10240
    constexpr int OFF_B0H = 2*OFF_AL;             // 20480
    constexpr int OFF_B0L = OFF_B0H + 64*SMSTRIDE*2;  // 25600
    constexpr int OFF_B1H = OFF_B0L + 64*SMSTRIDE*2;  // 30720
    constexpr int OFF_B1L = OFF_B1H + 64*SMSTRIDE*2;  // 35840
    constexpr int SS = FUSE ? (OFF_B1L + 64*SMSTRIDE*2) : OFF_B1H;

    const int tid = threadIdx.x;
    const int lane = tid & 31, warp = tid >> 5;
    const int wm = (warp >> 1) * 32, wn = (warp & 1) * 32;
    const int ar = lane & 15,            ac = (lane >> 4) << 3;
    const int br = (lane & 7) | ((lane >> 4) << 3), bc = ((lane >> 3) & 1) << 3;

    auto load_stage = [&](int kc, int s) {
        int k0 = kc * 32;
        char* base = smem + s * SS;
#pragma unroll
        for (int i = 0; i < 2; i++) {
            int idx = tid + i*256; int row = idx >> 2, ch = idx & 3;
            int so = (row*SMSTRIDE + ch*8) * 2;
            cp16(base + so,           Ah_g + (size_t)row*K + k0 + ch*8);
            cp16(base + OFF_AL + so,  Al_g + (size_t)row*K + k0 + ch*8);
        }
        {
            int row = tid >> 2, ch = tid & 3;
            int so = (row*SMSTRIDE + ch*8) * 2;
            size_t go = (size_t)row*K + k0 + ch*8;
            cp16(base + OFF_B0H + so, B0h + go);
            cp16(base + OFF_B0L + so, B0l + go);
            if (FUSE) {
                cp16(base + OFF_B1H + so, B1h + go);
                cp16(base + OFF_B1L + so, B1l + go);
            }
        }
    };

    float acc0[2][4][4], acc1[2][4][4];
#pragma unroll
    for (int i=0;i<2;i++)
#pragma unroll
    for (int j=0;j<4;j++)
#pragma unroll
    for (int k=0;k<4;k++) { acc0[i][j][k]=0.f; acc1[i][j][k]=0.f; }

    const int KC = K / 32;
    load_stage(0, 0); cp_commit();
    for (int kc = 0; kc < KC; kc++) {
        if (kc + 1 < KC) { load_stage(kc+1, (kc+1)&1); cp_commit(); cp_wait<1>(); }
        else             { cp_wait<0>(); }
        __syncthreads();
        char* base = smem + (kc & 1) * SS;
#pragma unroll
        for (int kk = 0; kk < 32; kk += 16) {
            uint32_t ahi[2][4], alo[2][4];
#pragma unroll
            for (int mt = 0; mt < 2; mt++) {
                int so = ((wm + mt*16 + ar)*SMSTRIDE + kk + ac) * 2;
                ldm4(ahi[mt], base + so);
                ldm4(alo[mt], base + OFF_AL + so);
            }
            uint32_t b0h[4][2], b0l[4][2], b1h[4][2], b1l[4][2];
#pragma unroll
            for (int p = 0; p < 2; p++) {
                int so = ((wn + p*16 + br)*SMSTRIDE + kk + bc) * 2;
                uint32_t r[4];
                ldm4(r, base + OFF_B0H + so);
                b0h[2*p][0]=r[0]; b0h[2*p][1]=r[1]; b0h[2*p+1][0]=r[2]; b0h[2*p+1][1]=r[3];
                ldm4(r, base + OFF_B0L + so);
                b0l[2*p][0]=r[0]; b0l[2*p][1]=r[1]; b0l[2*p+1][0]=r[2]; b0l[2*p+1][1]=r[3];
                if (FUSE) {
                    ldm4(r, base + OFF_B1H + so);
                    b1h[2*p][0]=r[0]; b1h[2*p][1]=r[1]; b1h[2*p+1][0]=r[2]; b1h[2*p+1][1]=r[3];
                    ldm4(r, base + OFF_B1L + so);
                    b1l[2*p][0]=r[0]; b1l[2*p][1]=r[1]; b1l[2*p+1][0]=r[2]; b1l[2*p+1][1]=r[3];
                }
            }
#pragma unroll
            for (int mt = 0; mt < 2; mt++)
#pragma unroll
            for (int nt = 0; nt < 4; nt++) {
                mma16816(acc0[mt][nt], ahi[mt], b0h[nt]);
                mma16816(acc0[mt][nt], ahi[mt], b0l[nt]);
                mma16816(acc0[mt][nt], alo[mt], b0h[nt]);
                if (FUSE) {
                    mma16816(acc1[mt][nt], ahi[mt], b1h[nt]);
                    mma16816(acc1[mt][nt], ahi[mt], b1l[nt]);
                    mma16816(acc1[mt][nt], alo[mt], b1h[nt]);
                }
            }
        }
        __syncthreads();
    }

    // epilogue
    int gp = lane >> 2, tq = lane & 3;
#pragma unroll
    for (int mt = 0; mt < 2; mt++)
#pragma unroll
    for (int nt = 0; nt < 4; nt++)
#pragma unroll
    for (int j = 0; j < 4; j++) {
        int r = row0 + wm + mt*16 + gp + ((j >> 1) << 3);
        int c = n0 + wn + nt*8 + tq*2 + (j & 1);
        if (FUSE) {
            float g = acc0[mt][nt][j], u = acc1[mt][nt][j];
            float wt = g_rowwt[r];
            float hv = (g / (1.f + __expf(-g))) * u * wt;
            __nv_bfloat16 h, l; bsplit(hv, h, l);
            g_Hhi[(size_t)r*DE + c] = h;
            g_Hlo[(size_t)r*DE + c] = l;
        } else {
            g_Y[(size_t)r*DH + c] = acc0[mt][nt][j];
        }
    }
}

// ---------------- 7. combine: out[t] = Y[shared] + Y[route0] + Y[route1] ----------------
__global__ void combine_kernel(float* __restrict__ out) {
    int gid = blockIdx.x * blockDim.x + threadIdx.x;
    if (gid >= NTOK * DH) return;
    int t = gid / DH, d = gid - t * DH;
    float v = g_Y[(size_t)(g_off[8] + t)*DH + d];
#pragma unroll
    for (int k = 0; k < 2; k++) {
        int code = g_route[t*2 + k];
        int e = code >> 20, s = code & 0xFFFFF;
        v += g_Y[(size_t)(g_off[e] + s)*DH + d];
    }
    out[gid] = v;
}

// ---------------- launch ----------------
extern "C" void kernel_launch(void* const* d_in, const int* in_sizes, int n_in,
                              void* d_out, int out_size) {
    const float* x     = (const float*)d_in[0];
    const float* Wg    = (const float*)d_in[1];
    const float* Wgate = (const float*)d_in[2];
    const float* Wup   = (const float*)d_in[3];
    const float* Wdown = (const float*)d_in[4];
    const float* Wsg   = (const float*)d_in[5];
    const float* Wsu   = (const float*)d_in[6];
    const float* Wsd   = (const float*)d_in[7];
    float* out = (float*)d_out;

    cudaFuncSetAttribute(gemm_kernel<true>,  cudaFuncAttributeMaxDynamicSharedMemorySize, 2*40960);
    cudaFuncSetAttribute(gemm_kernel<false>, cudaFuncAttributeMaxDynamicSharedMemorySize, 2*30720);

    init_kernel<<<1, 32>>>();
    router_kernel<<<NTOK/8, 256>>>(x, Wg);
    offsets_kernel<<<1, 32>>>();
    gather_kernel<<<MAXROWS, 256>>>(x);
    wsplit_kernel<0><<<dim3(DE/32, DH/32, 9), 256>>>(Wgate, Wsg);
    wsplit_kernel<1><<<dim3(DE/32, DH/32, 9), 256>>>(Wup,   Wsu);
    wsplit_kernel<2><<<dim3(DH/32, DE/32, 9), 256>>>(Wdown, Wsd);
    gemm_kernel<true><<<dim3(DE/64, MAXTILES), 256, 2*40960>>>();
    gemm_kernel<false><<<dim3(DH/64, MAXTILES), 256, 2*30720>>>();
    combine_kernel<<<(NTOK*DH)/256, 256>>>(out);
}

// round 7
// speedup vs baseline: 1.0002x; 1.0002x over previous
#include <cuda_runtime.h>
#include <cuda_bf16.h>
#include <cstdint>

#define NE    8
#define NTOK  4096
#define DH    2048
#define DE    1024
#define MAXTILES 104
#define MAXROWS  (MAXTILES*128)   // 13312

// ---------------- device-global scratch (static, no allocation) ----------------
__device__ __align__(16) __nv_bfloat16 g_Xhi[(size_t)MAXROWS*DH];
__device__ __align__(16) __nv_bfloat16 g_Xlo[(size_t)MAXROWS*DH];
__device__ __align__(16) __nv_bfloat16 g_Hhi[(size_t)MAXROWS*DE];
__device__ __align__(16) __nv_bfloat16 g_Hlo[(size_t)MAXROWS*DE];
__device__ __align__(16) float         g_Y  [(size_t)MAXROWS*DH];
// weights, bf16 hi/lo, transposed to [e][N][K] (K contiguous). 9th "expert" = shared.
__device__ __align__(16) __nv_bfloat16 g_Wgh[(size_t)9*DE*DH];
__device__ __align__(16) __nv_bfloat16 g_Wgl[(size_t)9*DE*DH];
__device__ __align__(16) __nv_bfloat16 g_Wuh[(size_t)9*DE*DH];
__device__ __align__(16) __nv_bfloat16 g_Wul[(size_t)9*DE*DH];
__device__ __align__(16) __nv_bfloat16 g_Wdh[(size_t)9*DE*DH];
__device__ __align__(16) __nv_bfloat16 g_Wdl[(size_t)9*DE*DH];

__device__ int   g_tok[NE*NTOK];
__device__ float g_wt [NE*NTOK];
__device__ int   g_cnt[NE];
__device__ int   g_off[10];
__device__ int   g_route[NTOK*2];     // (e<<20)|slot
__device__ float g_rowwt[MAXROWS];
__device__ int   g_tile_e[MAXTILES];
__device__ int   g_ntiles, g_total;

// ---------------- helpers ----------------
__device__ __forceinline__ void bsplit(float v, __nv_bfloat16& h, __nv_bfloat16& l) {
    h = __float2bfloat16(v);
    l = __float2bfloat16(v - __bfloat162float(h));
}
__device__ __forceinline__ void cp16(void* s, const void* g) {
    uint32_t sa = (uint32_t)__cvta_generic_to_shared(s);
    asm volatile("cp.async.cg.shared.global [%0], [%1], 16;\n" :: "r"(sa), "l"(g));
}
__device__ __forceinline__ void cp_commit() { asm volatile("cp.async.commit_group;\n"); }
template<int N> __device__ __forceinline__ void cp_wait() {
    asm volatile("cp.async.wait_group %0;\n" :: "n"(N));
}
__device__ __forceinline__ void ldm4(uint32_t* r, const void* p) {
    uint32_t a = (uint32_t)__cvta_generic_to_shared(p);
    asm volatile("ldmatrix.sync.aligned.m8n8.x4.shared.b16 {%0,%1,%2,%3},[%4];\n"
                 : "=r"(r[0]), "=r"(r[1]), "=r"(r[2]), "=r"(r[3]) : "r"(a));
}
__device__ __forceinline__ void mma16816(float* c, const uint32_t* a, const uint32_t* b) {
    asm volatile(
        "mma.sync.aligned.m16n8k16.row.col.f32.bf16.bf16.f32 "
        "{%0,%1,%2,%3},{%4,%5,%6,%7},{%8,%9},{%0,%1,%2,%3};\n"
        : "+f"(c[0]), "+f"(c[1]), "+f"(c[2]), "+f"(c[3])
        : "r"(a[0]), "r"(a[1]), "r"(a[2]), "r"(a[3]), "r"(b[0]), "r"(b[1]));
}

// ---------------- 1. init ----------------
__global__ void init_kernel() { if (threadIdx.x < NE) g_cnt[threadIdx.x] = 0; }

// ---------------- 2. router: warp per token ----------------
__global__ void router_kernel(const float* __restrict__ x, const float* __restrict__ Wg) {
    int warp = threadIdx.x >> 5, lane = threadIdx.x & 31;
    int t = blockIdx.x * 8 + warp;
    if (t >= NTOK) return;
    const float* xr = x + (size_t)t * DH;
    float acc[NE];
#pragma unroll
    for (int e = 0; e < NE; e++) acc[e] = 0.f;
    for (int d = lane; d < DH; d += 32) {
        float xv = xr[d];
        const float* wr = Wg + (size_t)d * NE;
#pragma unroll
        for (int e = 0; e < NE; e++) acc[e] += xv * wr[e];
    }
#pragma unroll
    for (int o = 16; o; o >>= 1)
#pragma unroll
        for (int e = 0; e < NE; e++) acc[e] += __shfl_down_sync(0xFFFFFFFFu, acc[e], o);
    if (lane == 0) {
        float m = acc[0];
#pragma unroll
        for (int e = 1; e < NE; e++) m = fmaxf(m, acc[e]);
        float p[NE], s = 0.f;
#pragma unroll
        for (int e = 0; e < NE; e++) { p[e] = __expf(acc[e] - m); s += p[e]; }
        float inv = 1.f / s;
#pragma unroll
        for (int e = 0; e < NE; e++) p[e] *= inv;
        int e0 = 0; float b0 = p[0];
#pragma unroll
        for (int e = 1; e < NE; e++) if (p[e] > b0) { b0 = p[e]; e0 = e; }
        int e1 = -1; float b1 = -1.f;
#pragma unroll
        for (int e = 0; e < NE; e++) if (e != e0 && p[e] > b1) { b1 = p[e]; e1 = e; }
        int s0 = atomicAdd(&g_cnt[e0], 1);
        g_tok[e0*NTOK + s0] = t; g_wt[e0*NTOK + s0] = b0;
        int s1 = atomicAdd(&g_cnt[e1], 1);
        g_tok[e1*NTOK + s1] = t; g_wt[e1*NTOK + s1] = b1;
        g_route[t*2 + 0] = (e0 << 20) | s0;
        g_route[t*2 + 1] = (e1 << 20) | s1;
    }
}

// ---------------- 3. offsets + tile map ----------------
__global__ void offsets_kernel() {
    if (threadIdx.x != 0) return;
    int off = 0, tc = 0;
    for (int e = 0; e < 9; e++) {
        g_off[e] = off;
        int c = (e < NE) ? g_cnt[e] : NTOK;
        int nt = (c + 127) >> 7;
        for (int i = 0; i < nt; i++) g_tile_e[tc + i] = e;
        tc += nt; off += nt << 7;
    }
    g_off[9] = off; g_ntiles = tc; g_total = off;
}

// ---------------- 4. gather + fp32->bf16 split (one block per padded row) ----------------
__global__ void gather_kernel(const float* __restrict__ x) {
    int r = blockIdx.x;
    if (r >= g_total) return;
    int e = 8;
#pragma unroll
    for (int i = 0; i < 9; i++) if (r < g_off[i+1]) { e = i; break; }
    int s = r - g_off[e];
    int t = -1; float wt = 0.f;
    if (e < NE) {
        if (s < g_cnt[e]) { t = g_tok[e*NTOK + s]; wt = g_wt[e*NTOK + s]; }
    } else { t = s; wt = 1.f; }
    if (threadIdx.x == 0) g_rowwt[r] = wt;
    __nv_bfloat16* dh = g_Xhi + (size_t)r * DH;
    __nv_bfloat16* dl = g_Xlo + (size_t)r * DH;
    if (t >= 0) {
        const float4* src = (const float4*)(x + (size_t)t * DH);
        for (int i = threadIdx.x; i < DH/4; i += blockDim.x) {
            float4 v = src[i];
            __nv_bfloat16 hx,lx,hy,ly,hz,lz,hw,lw;
            bsplit(v.x,hx,lx); bsplit(v.y,hy,ly); bsplit(v.z,hz,lz); bsplit(v.w,hw,lw);
            ((__nv_bfloat162*)dh)[i*2+0] = __nv_bfloat162(hx,hy);
            ((__nv_bfloat162*)dh)[i*2+1] = __nv_bfloat162(hz,hw);
            ((__nv_bfloat162*)dl)[i*2+0] = __nv_bfloat162(lx,ly);
            ((__nv_bfloat162*)dl)[i*2+1] = __nv_bfloat162(lz,lw);
        }
    } else {
        uint4 z = {0,0,0,0};
        for (int i = threadIdx.x; i < DH*2/16; i += blockDim.x) {
            ((uint4*)dh)[i] = z; ((uint4*)dl)[i] = z;
        }
    }
}

// ---------------- 5. weight transpose + split: [e][K][N] f32 -> [e][N][K] bf16 hi/lo ----
template<int W>  // 0=gate 1=up 2=down
__global__ void wsplit_kernel(const float* __restrict__ Wr, const float* __restrict__ Ws) {
    constexpr int K = (W == 2) ? DE : DH;
    constexpr int N = (W == 2) ? DH : DE;
    __nv_bfloat16* dh = (W==0) ? g_Wgh : (W==1) ? g_Wuh : g_Wdh;
    __nv_bfloat16* dl = (W==0) ? g_Wgl : (W==1) ? g_Wul : g_Wdl;
    int e = blockIdx.z;
    const float* src = (e < NE) ? (Wr + (size_t)e * K * N) : Ws;
    __nv_bfloat16* oh = dh + (size_t)e * K * N;
    __nv_bfloat16* ol = dl + (size_t)e * K * N;
    __shared__ float tile[32][33];
    int n0 = blockIdx.x * 32, k0 = blockIdx.y * 32;
    int tx = threadIdx.x & 31, ty = threadIdx.x >> 5;
#pragma unroll
    for (int j = 0; j < 4; j++) {
        int k = ty + j*8;
        tile[k][tx] = src[(size_t)(k0+k)*N + n0 + tx];
    }
    __syncthreads();
#pragma unroll
    for (int j = 0; j < 4; j++) {
        int n = ty + j*8;
        float v = tile[tx][n];
        __nv_bfloat16 h, l; bsplit(v, h, l);
        size_t o = (size_t)(n0+n)*K + k0 + tx;
        oh[o] = h; ol[o] = l;
    }
}

// ---------------- 6. grouped GEMM (mma.sync bf16, 3-term split) ----------------
// Block: 128M x 64N, 256 thr, warps 4x2, warp tile 32x32. K chunk 32, double-buffered.
// FUSE=1: A=Xhi/Xlo (K=2048), B=gate&up, epilogue silu(g)*u*wt -> Hhi/Hlo
// FUSE=0: A=Hhi/Hlo (K=1024), B=down, epilogue -> Y (f32)
#define SMSTRIDE 40   // elements per smem row (80B, conflict-free for ldmatrix)

template<bool FUSE>
__global__ void __launch_bounds__(256) gemm_kernel() {
    int tm = blockIdx.y;
    if (tm >= g_ntiles) return;
    constexpr int K = FUSE ? DH : DE;
    int e = g_tile_e[tm];
    int row0 = tm * 128;
    int n0 = blockIdx.x * 64;

    const __nv_bfloat16* Ah_g = (FUSE ? g_Xhi : g_Hhi) + (size_t)row0 * K;
    const __nv_bfloat16* Al_g = (FUSE ? g_Xlo : g_Hlo) + (size_t)row0 * K;
    const __nv_bfloat16* B0h = (FUSE ? g_Wgh : g_Wdh) + (size_t)e*DE*DH + (size_t)n0*K;
    const __nv_bfloat16* B0l = (FUSE ? g_Wgl : g_Wdl) + (size_t)e*DE*DH + (size_t)n0*K;
    const __nv_bfloat16* B1h = g_Wuh + (size_t)e*DE*DH + (size_t)n0*K;
    const __nv_bfloat16* B1l = g_Wul + (size_t)e*DE*DH + (size_t)n0*K;

    extern __shared__ char smem[];
    constexpr int OFF_AL = 128*SMSTRIDE*2;        // 10240
    constexpr int OFF_B0H = 2*OFF_AL;             // 20480
    constexpr int OFF_B0L = OFF_B0H + 64*SMSTRIDE*2;  // 25600
    constexpr int OFF_B1H = OFF_B0L + 64*SMSTRIDE*2;  // 30720
    constexpr int OFF_B1L = OFF_B1H + 64*SMSTRIDE*2;  // 35840
    constexpr int SS = FUSE ? (OFF_B1L + 64*SMSTRIDE*2) : OFF_B1H;

    const int tid = threadIdx.x;
    const int lane = tid & 31, warp = tid >> 5;
    const int wm = (warp >> 1) * 32, wn = (warp & 1) * 32;
    const int ar = lane & 15,            ac = (lane >> 4) << 3;
    const int br = (lane & 7) | ((lane >> 4) << 3), bc = ((lane >> 3) & 1) << 3;

    auto load_stage = [&](int kc, int s) {
        int k0 = kc * 32;
        char* base = smem + s * SS;
#pragma unroll
        for (int i = 0; i < 2; i++) {
            int idx = tid + i*256; int row = idx >> 2, ch = idx & 3;
            int so = (row*SMSTRIDE + ch*8) * 2;
            cp16(base + so,           Ah_g + (size_t)row*K + k0 + ch*8);
            cp16(base + OFF_AL + so,  Al_g + (size_t)row*K + k0 + ch*8);
        }
        {
            int row = tid >> 2, ch = tid & 3;
            int so = (row*SMSTRIDE + ch*8) * 2;
            size_t go = (size_t)row*K + k0 + ch*8;
            cp16(base + OFF_B0H + so, B0h + go);
            cp16(base + OFF_B0L + so, B0l + go);
            if (FUSE) {
                cp16(base + OFF_B1H + so, B1h + go);
                cp16(base + OFF_B1L + so, B1l + go);
            }
        }
    };

    float acc0[2][4][4], acc1[2][4][4];
#pragma unroll
    for (int i=0;i<2;i++)
#pragma unroll
    for (int j=0;j<4;j++)
#pragma unroll
    for (int k=0;k<4;k++) { acc0[i][j][k]=0.f; acc1[i][j][k]=0.f; }

    const int KC = K / 32;
    load_stage(0, 0); cp_commit();
    for (int kc = 0; kc < KC; kc++) {
        if (kc + 1 < KC) { load_stage(kc+1, (kc+1)&1); cp_commit(); cp_wait<1>(); }
        else             { cp_wait<0>(); }
        __syncthreads();
        char* base = smem + (kc & 1) * SS;
#pragma unroll
        for (int kk = 0; kk < 32; kk += 16) {
            uint32_t ahi[2][4], alo[2][4];
#pragma unroll
            for (int mt = 0; mt < 2; mt++) {
                int so = ((wm + mt*16 + ar)*SMSTRIDE + kk + ac) * 2;
                ldm4(ahi[mt], base + so);
                ldm4(alo[mt], base + OFF_AL + so);
            }
            uint32_t b0h[4][2], b0l[4][2], b1h[4][2], b1l[4][2];
#pragma unroll
            for (int p = 0; p < 2; p++) {
                int so = ((wn + p*16 + br)*SMSTRIDE + kk + bc) * 2;
                uint32_t r[4];
                ldm4(r, base + OFF_B0H + so);
                b0h[2*p][0]=r[0]; b0h[2*p][1]=r[1]; b0h[2*p+1][0]=r[2]; b0h[2*p+1][1]=r[3];
                ldm4(r, base + OFF_B0L + so);
                b0l[2*p][0]=r[0]; b0l[2*p][1]=r[1]; b0l[2*p+1][0]=r[2]; b0l[2*p+1][1]=r[3];
                if (FUSE) {
                    ldm4(r, base + OFF_B1H + so);
                    b1h[2*p][0]=r[0]; b1h[2*p][1]=r[1]; b1h[2*p+1][0]=r[2]; b1h[2*p+1][1]=r[3];
                    ldm4(r, base + OFF_B1L + so);
                    b1l[2*p][0]=r[0]; b1l[2*p][1]=r[1]; b1l[2*p+1][0]=r[2]; b1l[2*p+1][1]=r[3];
                }
            }
#pragma unroll
            for (int mt = 0; mt < 2; mt++)
#pragma unroll
            for (int nt = 0; nt < 4; nt++) {
                mma16816(acc0[mt][nt], ahi[mt], b0h[nt]);
                mma16816(acc0[mt][nt], ahi[mt], b0l[nt]);
                mma16816(acc0[mt][nt], alo[mt], b0h[nt]);
                if (FUSE) {
                    mma16816(acc1[mt][nt], ahi[mt], b1h[nt]);
                    mma16816(acc1[mt][nt], ahi[mt], b1l[nt]);
                    mma16816(acc1[mt][nt], alo[mt], b1h[nt]);
                }
            }
        }
        __syncthreads();
    }

    // epilogue
    int gp = lane >> 2, tq = lane & 3;
#pragma unroll
    for (int mt = 0; mt < 2; mt++)
#pragma unroll
    for (int nt = 0; nt < 4; nt++)
#pragma unroll
    for (int j = 0; j < 4; j++) {
        int r = row0 + wm + mt*16 + gp + ((j >> 1) << 3);
        int c = n0 + wn + nt*8 + tq*2 + (j & 1);
        if (FUSE) {
            float g = acc0[mt][nt][j], u = acc1[mt][nt][j];
            float wt = g_rowwt[r];
            float hv = (g / (1.f + __expf(-g))) * u * wt;
            __nv_bfloat16 h, l; bsplit(hv, h, l);
            g_Hhi[(size_t)r*DE + c] = h;
            g_Hlo[(size_t)r*DE + c] = l;
        } else {
            g_Y[(size_t)r*DH + c] = acc0[mt][nt][j];
        }
    }
}

// ---------------- 7. combine: out[t] = Y[shared] + Y[route0] + Y[route1] ----------------
__global__ void combine_kernel(float* __restrict__ out) {
    int gid = blockIdx.x * blockDim.x + threadIdx.x;
    if (gid >= NTOK * DH) return;
    int t = gid / DH, d = gid - t * DH;
    float v = g_Y[(size_t)(g_off[8] + t)*DH + d];
#pragma unroll
    for (int k = 0; k < 2; k++) {
        int code = g_route[t*2 + k];
        int e = code >> 20, s = code & 0xFFFFF;
        v += g_Y[(size_t)(g_off[e] + s)*DH + d];
    }
    out[gid] = v;
}

// ---------------- launch ----------------
extern "C" void kernel_launch(void* const* d_in, const int* in_sizes, int n_in,
                              void* d_out, int out_size) {
    const float* x     = (const float*)d_in[0];
    const float* Wg    = (const float*)d_in[1];
    const float* Wgate = (const float*)d_in[2];
    const float* Wup   = (const float*)d_in[3];
    const float* Wdown = (const float*)d_in[4];
    const float* Wsg   = (const float*)d_in[5];
    const float* Wsu   = (const float*)d_in[6];
    const float* Wsd   = (const float*)d_in[7];
    float* out = (float*)d_out;

    cudaFuncSetAttribute(gemm_kernel<true>,  cudaFuncAttributeMaxDynamicSharedMemorySize, 2*40960);
    cudaFuncSetAttribute(gemm_kernel<false>, cudaFuncAttributeMaxDynamicSharedMemorySize, 2*30720);

    init_kernel<<<1, 32>>>();
    router_kernel<<<NTOK/8, 256>>>(x, Wg);
    offsets_kernel<<<1, 32>>>();
    gather_kernel<<<MAXROWS, 256>>>(x);
    wsplit_kernel<0><<<dim3(DE/32, DH/32, 9), 256>>>(Wgate, Wsg);
    wsplit_kernel<1><<<dim3(DE/32, DH/32, 9), 256>>>(Wup,   Wsu);
    wsplit_kernel<2><<<dim3(DH/32, DE/32, 9), 256>>>(Wdown, Wsd);
    gemm_kernel<true><<<dim3(DE/64, MAXTILES), 256, 2*40960>>>();
    gemm_kernel<false><<<dim3(DH/64, MAXTILES), 256, 2*30720>>>();
    combine_kernel<<<(NTOK*DH)/256, 256>>>(out);
}

// round 10
// speedup vs baseline: 1.3809x; 1.3806x over previous
#include <cuda_runtime.h>
#include <cuda_fp16.h>
#include <cstdint>

#define NE    8
#define NTOK  4096
#define DH    2048
#define DE    1024
#define MAXTILES 104
#define MAXROWS  (MAXTILES*128)   // 13312

// ---------------- device-global scratch (static, no allocation) ----------------
__device__ __align__(16) __half g_Xhi[(size_t)MAXROWS*DH];
__device__ __align__(16) __half g_Xlo[(size_t)MAXROWS*DH];
__device__ __align__(16) __half g_Hhi[(size_t)MAXROWS*DE];
__device__ __align__(16) __half g_Hlo[(size_t)MAXROWS*DE];
__device__ __align__(16) float  g_Y  [(size_t)MAXROWS*DH];
// weights, fp16 hi only, transposed to [e][N][K] (K contiguous). 9th "expert" = shared.
__device__ __align__(16) __half g_Wgh[(size_t)9*DE*DH];
__device__ __align__(16) __half g_Wuh[(size_t)9*DE*DH];
__device__ __align__(16) __half g_Wdh[(size_t)9*DE*DH];

__device__ int   g_tok[NE*NTOK];
__device__ float g_wt [NE*NTOK];
__device__ int   g_cnt[NE];
__device__ int   g_off[10];
__device__ int   g_route[NTOK*2];     // (e<<20)|slot
__device__ float g_rowwt[MAXROWS];
__device__ int   g_tile_e[MAXTILES];
__device__ int   g_ntiles, g_total;

// ---------------- helpers ----------------
__device__ __forceinline__ void hsplit(float v, __half& h, __half& l) {
    h = __float2half(v);
    l = __float2half(v - __half2float(h));
}
__device__ __forceinline__ void cp16s(uint32_t s, const void* g) {
    asm volatile("cp.async.cg.shared.global [%0], [%1], 16;\n" :: "r"(s), "l"(g));
}
__device__ __forceinline__ void cp_commit() { asm volatile("cp.async.commit_group;\n"); }
template<int N> __device__ __forceinline__ void cp_wait() {
    asm volatile("cp.async.wait_group %0;\n" :: "n"(N));
}
__device__ __forceinline__ void ldm4(uint32_t* r, const void* p) {
    uint32_t a = (uint32_t)__cvta_generic_to_shared(p);
    asm volatile("ldmatrix.sync.aligned.m8n8.x4.shared.b16 {%0,%1,%2,%3},[%4];\n"
                 : "=r"(r[0]), "=r"(r[1]), "=r"(r[2]), "=r"(r[3]) : "r"(a));
}
__device__ __forceinline__ void mma16816(float* c, const uint32_t* a, const uint32_t* b) {
    asm volatile(
        "mma.sync.aligned.m16n8k16.row.col.f32.f16.f16.f32 "
        "{%0,%1,%2,%3},{%4,%5,%6,%7},{%8,%9},{%0,%1,%2,%3};\n"
        : "+f"(c[0]), "+f"(c[1]), "+f"(c[2]), "+f"(c[3])
        : "r"(a[0]), "r"(a[1]), "r"(a[2]), "r"(a[3]), "r"(b[0]), "r"(b[1]));
}

// ---------------- 1. init ----------------
__global__ void init_kernel() { if (threadIdx.x < NE) g_cnt[threadIdx.x] = 0; }

// ---------------- 2. router: warp per token ----------------
__global__ void router_kernel(const float* __restrict__ x, const float* __restrict__ Wg) {
    int warp = threadIdx.x >> 5, lane = threadIdx.x & 31;
    int t = blockIdx.x * 8 + warp;
    if (t >= NTOK) return;
    const float* xr = x + (size_t)t * DH;
    float acc[NE];
#pragma unroll
    for (int e = 0; e < NE; e++) acc[e] = 0.f;
    for (int d = lane; d < DH; d += 32) {
        float xv = xr[d];
        const float* wr = Wg + (size_t)d * NE;
#pragma unroll
        for (int e = 0; e < NE; e++) acc[e] += xv * wr[e];
    }
#pragma unroll
    for (int o = 16; o; o >>= 1)
#pragma unroll
        for (int e = 0; e < NE; e++) acc[e] += __shfl_down_sync(0xFFFFFFFFu, acc[e], o);
    if (lane == 0) {
        float m = acc[0];
#pragma unroll
        for (int e = 1; e < NE; e++) m = fmaxf(m, acc[e]);
        float p[NE], s = 0.f;
#pragma unroll
        for (int e = 0; e < NE; e++) { p[e] = __expf(acc[e] - m); s += p[e]; }
        float inv = 1.f / s;
#pragma unroll
        for (int e = 0; e < NE; e++) p[e] *= inv;
        int e0 = 0; float b0 = p[0];
#pragma unroll
        for (int e = 1; e < NE; e++) if (p[e] > b0) { b0 = p[e]; e0 = e; }
        int e1 = -1; float b1 = -1.f;
#pragma unroll
        for (int e = 0; e < NE; e++) if (e != e0 && p[e] > b1) { b1 = p[e]; e1 = e; }
        int s0 = atomicAdd(&g_cnt[e0], 1);
        g_tok[e0*NTOK + s0] = t; g_wt[e0*NTOK + s0] = b0;
        int s1 = atomicAdd(&g_cnt[e1], 1);
        g_tok[e1*NTOK + s1] = t; g_wt[e1*NTOK + s1] = b1;
        g_route[t*2 + 0] = (e0 << 20) | s0;
        g_route[t*2 + 1] = (e1 << 20) | s1;
    }
}

// ---------------- 3. offsets + tile map ----------------
__global__ void offsets_kernel() {
    if (threadIdx.x != 0) return;
    int off = 0, tc = 0;
    for (int e = 0; e < 9; e++) {
        g_off[e] = off;
        int c = (e < NE) ? g_cnt[e] : NTOK;
        int nt = (c + 127) >> 7;
        for (int i = 0; i < nt; i++) g_tile_e[tc + i] = e;
        tc += nt; off += nt << 7;
    }
    g_off[9] = off; g_ntiles = tc; g_total = off;
}

// ---------------- 4. gather + fp32->fp16 hi/lo split ----------------
__global__ void gather_kernel(const float* __restrict__ x) {
    int r = blockIdx.x;
    if (r >= g_total) return;
    int e = 8;
#pragma unroll
    for (int i = 0; i < 9; i++) if (r < g_off[i+1]) { e = i; break; }
    int s = r - g_off[e];
    int t = -1; float wt = 0.f;
    if (e < NE) {
        if (s < g_cnt[e]) { t = g_tok[e*NTOK + s]; wt = g_wt[e*NTOK + s]; }
    } else { t = s; wt = 1.f; }
    if (threadIdx.x == 0) g_rowwt[r] = wt;
    __half* dh = g_Xhi + (size_t)r * DH;
    __half* dl = g_Xlo + (size_t)r * DH;
    if (t >= 0) {
        const float4* src = (const float4*)(x + (size_t)t * DH);
        for (int i = threadIdx.x; i < DH/4; i += blockDim.x) {
            float4 v = src[i];
            __half hx,lx,hy,ly,hz,lz,hw,lw;
            hsplit(v.x,hx,lx); hsplit(v.y,hy,ly); hsplit(v.z,hz,lz); hsplit(v.w,hw,lw);
            ((__half2*)dh)[i*2+0] = __halves2half2(hx,hy);
            ((__half2*)dh)[i*2+1] = __halves2half2(hz,hw);
            ((__half2*)dl)[i*2+0] = __halves2half2(lx,ly);
            ((__half2*)dl)[i*2+1] = __halves2half2(lz,lw);
        }
    } else {
        uint4 z = {0,0,0,0};
        for (int i = threadIdx.x; i < DH*2/16; i += blockDim.x) {
            ((uint4*)dh)[i] = z; ((uint4*)dl)[i] = z;
        }
    }
}

// ---------------- 5. weight transpose + fp16 convert: [e][K][N] -> [e][N][K] ----
template<int W>  // 0=gate 1=up 2=down
__global__ void wsplit_kernel(const float* __restrict__ Wr, const float* __restrict__ Ws) {
    constexpr int K = (W == 2) ? DE : DH;
    constexpr int N = (W == 2) ? DH : DE;
    __half* dh = (W==0) ? g_Wgh : (W==1) ? g_Wuh : g_Wdh;
    int e = blockIdx.z;
    const float* src = (e < NE) ? (Wr + (size_t)e * K * N) : Ws;
    __half* oh = dh + (size_t)e * K * N;
    __shared__ float tile[32][33];
    int n0 = blockIdx.x * 32, k0 = blockIdx.y * 32;
    int tx = threadIdx.x & 31, ty = threadIdx.x >> 5;
#pragma unroll
    for (int j = 0; j < 4; j++) {
        int k = ty + j*8;
        tile[k][tx] = src[(size_t)(k0+k)*N + n0 + tx];
    }
    __syncthreads();
#pragma unroll
    for (int j = 0; j < 4; j++) {
        int n = ty + j*8;
        oh[(size_t)(n0+n)*K + k0 + tx] = __float2half(tile[tx][n]);
    }
}

// ---------------- 6. grouped GEMM: fp16 mma.sync, 2-term split (A hi/lo, B hi) --
// Block: 128M x 128N, 512 thr (4x4 warps), warp tile 32x32. K chunk 32, 2 stages.
// FUSE=1: A=Xhi/Xlo (K=2048), B=gate&up; epilogue silu(g)*u*wt -> Hhi/Hlo fp16
// FUSE=0: A=Hhi/Hlo (K=1024), B=down;    epilogue -> Y fp32
#define SMROW 80   // bytes per smem row (40 halfs: 32 data + 8 pad)

template<bool FUSE>
__global__ void __launch_bounds__(512, 1) gemm_hmma() {
    int tm = blockIdx.y;
    if (tm >= g_ntiles) return;
    constexpr int K = FUSE ? DH : DE;
    constexpr int KC = K / 32;
    constexpr int NMAT = FUSE ? 4 : 3;
    constexpr int MATB = 128 * SMROW;       // 10240
    constexpr int STAGE = NMAT * MATB;
    int e = g_tile_e[tm];
    int row0 = tm * 128;
    int n0 = blockIdx.x * 128;

    const __half* gm[NMAT];
    gm[0] = (FUSE ? g_Xhi : g_Hhi) + (size_t)row0 * K;
    gm[1] = (FUSE ? g_Xlo : g_Hlo) + (size_t)row0 * K;
    size_t wb = (size_t)e * DE * DH + (size_t)n0 * K;
    gm[2] = (FUSE ? g_Wgh : g_Wdh) + wb;
    if (FUSE) gm[3] = g_Wuh + wb;

    extern __shared__ char smem[];
    const int tid = threadIdx.x, lane = tid & 31, warp = tid >> 5;
    const int wm = (warp >> 2) * 32, wn = (warp & 3) * 32;
    const int ar = lane & 15,            ac = (lane >> 4) << 3;
    const int br = (lane & 7) | ((lane >> 4) << 3), bc = ((lane >> 3) & 1) << 3;
    const int gp = lane >> 2, tq = lane & 3;

    const int lr = tid >> 2, lc = tid & 3;   // stage-load row / 16B chunk

    auto load_stage = [&](int kc, int buf) {
        char* base = smem + buf * STAGE;
        int k0 = kc * 32;
#pragma unroll
        for (int m = 0; m < NMAT; m++) {
            cp16s((uint32_t)__cvta_generic_to_shared(base + m*MATB + lr*SMROW + lc*16),
                  gm[m] + (size_t)lr * K + k0 + lc*8);
        }
    };

    float acc0[2][4][4], acc1[2][4][4];
#pragma unroll
    for (int i=0;i<2;i++)
#pragma unroll
    for (int j=0;j<4;j++)
#pragma unroll
    for (int k=0;k<4;k++) { acc0[i][j][k]=0.f; acc1[i][j][k]=0.f; }

    load_stage(0, 0); cp_commit();
    for (int kc = 0; kc < KC; kc++) {
        if (kc + 1 < KC) { load_stage(kc+1, (kc+1)&1); cp_commit(); cp_wait<1>(); }
        else             { cp_wait<0>(); }
        __syncthreads();
        char* base = smem + (kc & 1) * STAGE;
#pragma unroll
        for (int kk = 0; kk < 32; kk += 16) {
            uint32_t ahi[2][4], alo[2][4];
#pragma unroll
            for (int mt = 0; mt < 2; mt++) {
                int so = (wm + mt*16 + ar)*SMROW + (kk + ac)*2;
                ldm4(ahi[mt], base + so);
                ldm4(alo[mt], base + MATB + so);
            }
            uint32_t b0[4][2], b1[4][2];
#pragma unroll
            for (int p = 0; p < 2; p++) {
                int so = (wn + p*16 + br)*SMROW + (kk + bc)*2;
                uint32_t r4[4];
                ldm4(r4, base + 2*MATB + so);
                b0[2*p][0]=r4[0]; b0[2*p][1]=r4[1]; b0[2*p+1][0]=r4[2]; b0[2*p+1][1]=r4[3];
                if (FUSE) {
                    ldm4(r4, base + 3*MATB + so);
                    b1[2*p][0]=r4[0]; b1[2*p][1]=r4[1]; b1[2*p+1][0]=r4[2]; b1[2*p+1][1]=r4[3];
                }
            }
#pragma unroll
            for (int mt = 0; mt < 2; mt++)
#pragma unroll
            for (int nt = 0; nt < 4; nt++) {
                mma16816(acc0[mt][nt], ahi[mt], b0[nt]);
                mma16816(acc0[mt][nt], alo[mt], b0[nt]);
                if (FUSE) {
                    mma16816(acc1[mt][nt], ahi[mt], b1[nt]);
                    mma16816(acc1[mt][nt], alo[mt], b1[nt]);
                }
            }
        }
        __syncthreads();
    }

    // ---------------- epilogue ----------------
    if (FUSE) {
        float wt[2][2];
#pragma unroll
        for (int mt = 0; mt < 2; mt++)
#pragma unroll
        for (int jj = 0; jj < 2; jj++)
            wt[mt][jj] = g_rowwt[row0 + wm + mt*16 + gp + jj*8];
#pragma unroll
        for (int mt = 0; mt < 2; mt++)
#pragma unroll
        for (int nt = 0; nt < 4; nt++)
#pragma unroll
        for (int jj = 0; jj < 2; jj++) {
            int r = row0 + wm + mt*16 + gp + jj*8;
            int c = n0 + wn + nt*8 + tq*2;
            float g0 = acc0[mt][nt][jj*2], g1 = acc0[mt][nt][jj*2+1];
            float u0 = acc1[mt][nt][jj*2], u1 = acc1[mt][nt][jj*2+1];
            float w  = wt[mt][jj];
            float h0 = (g0 / (1.f + __expf(-g0))) * u0 * w;
            float h1 = (g1 / (1.f + __expf(-g1))) * u1 * w;
            __half h0h,h0l,h1h,h1l;
            hsplit(h0,h0h,h0l); hsplit(h1,h1h,h1l);
            *(__half2*)(g_Hhi + (size_t)r*DE + c) = __halves2half2(h0h, h1h);
            *(__half2*)(g_Hlo + (size_t)r*DE + c) = __halves2half2(h0l, h1l);
        }
    } else {
#pragma unroll
        for (int mt = 0; mt < 2; mt++)
#pragma unroll
        for (int nt = 0; nt < 4; nt++)
#pragma unroll
        for (int jj = 0; jj < 2; jj++) {
            int r = row0 + wm + mt*16 + gp + jj*8;
            int c = n0 + wn + nt*8 + tq*2;
            *(float2*)(g_Y + (size_t)r*DH + c) =
                make_float2(acc0[mt][nt][jj*2], acc0[mt][nt][jj*2+1]);
        }
    }
}

// ---------------- 7. combine ----------------
__global__ void combine_kernel(float* __restrict__ out) {
    int gid = blockIdx.x * blockDim.x + threadIdx.x;
    if (gid >= NTOK * DH) return;
    int t = gid / DH, d = gid - t * DH;
    float v = g_Y[(size_t)(g_off[8] + t)*DH + d];
#pragma unroll
    for (int k = 0; k < 2; k++) {
        int code = g_route[t*2 + k];
        int e = code >> 20, s = code & 0xFFFFF;
        v += g_Y[(size_t)(g_off[e] + s)*DH + d];
    }
    out[gid] = v;
}

// ---------------- launch ----------------
extern "C" void kernel_launch(void* const* d_in, const int* in_sizes, int n_in,
                              void* d_out, int out_size) {
    const float* x     = (const float*)d_in[0];
    const float* Wg    = (const float*)d_in[1];
    const float* Wgate = (const float*)d_in[2];
    const float* Wup   = (const float*)d_in[3];
    const float* Wdown = (const float*)d_in[4];
    const float* Wsg   = (const float*)d_in[5];
    const float* Wsu   = (const float*)d_in[6];
    const float* Wsd   = (const float*)d_in[7];
    float* out = (float*)d_out;

    const int FUSE_SMEM = 2 * 4 * 128 * SMROW;  // 81920
    const int DOWN_SMEM = 2 * 3 * 128 * SMROW;  // 61440
    cudaFuncSetAttribute(gemm_hmma<true>,  cudaFuncAttributeMaxDynamicSharedMemorySize, FUSE_SMEM);
    cudaFuncSetAttribute(gemm_hmma<false>, cudaFuncAttributeMaxDynamicSharedMemorySize, DOWN_SMEM);

    init_kernel<<<1, 32>>>();
    router_kernel<<<NTOK/8, 256>>>(x, Wg);
    offsets_kernel<<<1, 32>>>();
    gather_kernel<<<MAXROWS, 256>>>(x);
    wsplit_kernel<0><<<dim3(DE/32, DH/32, 9), 256>>>(Wgate, Wsg);
    wsplit_kernel<1><<<dim3(DE/32, DH/32, 9), 256>>>(Wup,   Wsu);
    wsplit_kernel<2><<<dim3(DH/32, DE/32, 9), 256>>>(Wdown, Wsd);
    gemm_hmma<true><<<dim3(DE/128, MAXTILES), 512, FUSE_SMEM>>>();
    gemm_hmma<false><<<dim3(DH/128, MAXTILES), 512, DOWN_SMEM>>>();
    combine_kernel<<<(NTOK*DH)/256, 256>>>(out);
}